// round 8
// baseline (speedup 1.0000x reference)
#include <cuda_runtime.h>

// ---------------------------------------------------------------------------
// CausalEdgeAttention — algebraically reduced, 2-pass recompute (no h store).
//   out = edge_attr + 0.5*((relu(ctx@W1+b1) * g) @ M + const8)
//   ctx = 0.5*(nf[src]+nf[tgt]);  M = n_W2@Wv@Wo@Wp (256x8)
// R7: revert store-h (uncoalesced 256MB scatter killed R6). f32 everywhere.
//     kStats: smem packed weights + launch_bounds(128,6) for occupancy.
//     kOut:   1 edge/thread, minimal FMA2 chains, launch_bounds(256,3).
// ---------------------------------------------------------------------------

#define STATS_BLOCKS 888               // 6 blocks/SM * 148 SMs
#define STATS_WARPS  (STATS_BLOCKS * 4)

__device__ __align__(16) float g_U[256 * 8];
__device__ __align__(16) float g_V[256 * 8];
__device__ __align__(16) float g_M[256 * 8];
__device__ __align__(16) float g_Mg[256 * 8];
__device__ float g_c1[256];
__device__ float g_c2[256];
__device__ float g_c3[8];
__device__ __align__(16) float g_const8[8];
__device__ __align__(16) float g_part[STATS_BLOCKS * 512];

// ---- packed f32x2 helpers -------------------------------------------------
__device__ __forceinline__ unsigned long long pk2(float lo, float hi) {
    unsigned long long r;
    asm("mov.b64 %0, {%1, %2};" : "=l"(r) : "f"(lo), "f"(hi));
    return r;
}
__device__ __forceinline__ void upk2(unsigned long long v, float& lo, float& hi) {
    asm("mov.b64 {%0, %1}, %2;" : "=f"(lo), "=f"(hi) : "l"(v));
}
#define FMA2(d, a, b, c) asm("fma.rn.f32x2 %0, %1, %2, %3;" : "=l"(d) : "l"(a), "l"(b), "l"(c))
#define ADD2(d, a, b)    asm("add.rn.f32x2 %0, %1, %2;" : "=l"(d) : "l"(a), "l"(b))

#define HALF2C 0x3F0000003F000000ULL   // (0.5f, 0.5f)

// ---- pass 1: batch stats of h = relu((a+b)@(W1/2)+b1) ---------------------
// warp-per-edge, lane owns cols j=32k+lane; weights packed (0.5 folded) in smem.
__global__ void __launch_bounds__(128, 6) kStats(
    const float* __restrict__ nf, const int* __restrict__ ei,
    const float* __restrict__ W1, const float* __restrict__ b1, int E) {
    __shared__ ulonglong2 sW01[256];        // col j: (w0,w1),(w2,w3) * 0.5
    __shared__ ulonglong2 sW45[256];        // col j: (w4,w5),(w6,w7) * 0.5
    __shared__ unsigned long long sB2[256]; // (b1[j], 0)
    __shared__ float psum[4][256];
    __shared__ float psq[4][256];

    int tid = threadIdx.x;
    int lane = tid & 31;
    int w = tid >> 5;

    for (int j = tid; j < 256; j += 128) {
        ulonglong2 va, vb;
        va.x = pk2(0.5f * W1[0 * 256 + j], 0.5f * W1[1 * 256 + j]);
        va.y = pk2(0.5f * W1[2 * 256 + j], 0.5f * W1[3 * 256 + j]);
        vb.x = pk2(0.5f * W1[4 * 256 + j], 0.5f * W1[5 * 256 + j]);
        vb.y = pk2(0.5f * W1[6 * 256 + j], 0.5f * W1[7 * 256 + j]);
        sW01[j] = va;
        sW45[j] = vb;
        sB2[j] = pk2(b1[j], 0.f);
    }
    __syncthreads();

    float s[8], q[8];
#pragma unroll
    for (int k = 0; k < 8; k++) { s[k] = 0.f; q[k] = 0.f; }

    int gw = blockIdx.x * 4 + w;
    int per = (((E + STATS_WARPS - 1) / STATS_WARPS) + 1) & ~1;   // even
    int e0 = gw * per;
    int e1 = min(e0 + per, E);
    bool evenE = ((E & 1) == 0);

    const ulonglong4* nfq = (const ulonglong4*)nf;

    for (int e = e0; e < e1; e += 2) {
        bool two = (e + 1 < e1);
        int ia0, ib0, ia1, ib1;
        if (two && evenE) {
            int2 s2 = *(const int2*)(ei + e);
            int2 t2 = *(const int2*)(ei + E + e);
            ia0 = s2.x; ia1 = s2.y; ib0 = t2.x; ib1 = t2.y;
        } else {
            ia0 = ei[e]; ib0 = ei[E + e];
            int et = two ? (e + 1) : e;
            ia1 = ei[et]; ib1 = ei[E + et];
        }

        ulonglong4 A0 = nfq[ia0], B0 = nfq[ib0];
        ulonglong4 A1 = nfq[ia1], B1 = nfq[ib1];

        // ctx sums (0.5 folded into weights)
        unsigned long long c0[4], c1[4];
        ADD2(c0[0], A0.x, B0.x); ADD2(c0[1], A0.y, B0.y);
        ADD2(c0[2], A0.z, B0.z); ADD2(c0[3], A0.w, B0.w);
        ADD2(c1[0], A1.x, B1.x); ADD2(c1[1], A1.y, B1.y);
        ADD2(c1[2], A1.z, B1.z); ADD2(c1[3], A1.w, B1.w);

#pragma unroll
        for (int k = 0; k < 8; k++) {
            int j = k * 32 + lane;
            ulonglong2 wA = sW01[j];
            ulonglong2 wB = sW45[j];
            unsigned long long b2 = sB2[j];
            unsigned long long t;
            float lo, hi;

            // edge 0
            FMA2(t, c0[0], wA.x, b2);
            FMA2(t, c0[1], wA.y, t);
            FMA2(t, c0[2], wB.x, t);
            FMA2(t, c0[3], wB.y, t);
            upk2(t, lo, hi);
            float h0 = fmaxf(lo + hi, 0.f);
            s[k] += h0;
            q[k] = fmaf(h0, h0, q[k]);

            // edge 1
            FMA2(t, c1[0], wA.x, b2);
            FMA2(t, c1[1], wA.y, t);
            FMA2(t, c1[2], wB.x, t);
            FMA2(t, c1[3], wB.y, t);
            upk2(t, lo, hi);
            float h1 = fmaxf(lo + hi, 0.f);
            if (two) {
                s[k] += h1;
                q[k] = fmaf(h1, h1, q[k]);
            }
        }
    }

#pragma unroll
    for (int k = 0; k < 8; k++) {
        psum[w][k * 32 + lane] = s[k];
        psq[w][k * 32 + lane] = q[k];
    }
    __syncthreads();

    for (int c = tid; c < 256; c += 128) {
        float ts = 0.f, tq = 0.f;
#pragma unroll
        for (int ww = 0; ww < 4; ww++) { ts += psum[ww][c]; tq += psq[ww][c]; }
        g_part[blockIdx.x * 512 + c] = ts;
        g_part[blockIdx.x * 512 + 256 + c] = tq;
    }
}

// ---- weight folding + BN finalize, single kernel --------------------------
__global__ void __launch_bounds__(1024) kFoldFin(
    const float* __restrict__ Wo, const float* __restrict__ Wp,
    const float* __restrict__ nb2, const float* __restrict__ Wv,
    const float* __restrict__ bv, const float* __restrict__ bo,
    const float* __restrict__ nW2, const float* __restrict__ bp,
    const float* __restrict__ gamma, const float* __restrict__ beta,
    float invE) {
    int tid = threadIdx.x;

    // stage A: U = Wo@Wp ; c1 = nb2@Wv + bv
    for (int t = tid; t < 2304; t += 1024) {
        if (t < 2048) {
            int i = t >> 3, d = t & 7;
            float a0 = 0.f, a1 = 0.f, a2 = 0.f, a3 = 0.f;
            for (int k = 0; k < 256; k += 4) {
                a0 = fmaf(Wo[i * 256 + k],     Wp[k * 8 + d],       a0);
                a1 = fmaf(Wo[i * 256 + k + 1], Wp[(k + 1) * 8 + d], a1);
                a2 = fmaf(Wo[i * 256 + k + 2], Wp[(k + 2) * 8 + d], a2);
                a3 = fmaf(Wo[i * 256 + k + 3], Wp[(k + 3) * 8 + d], a3);
            }
            g_U[t] = (a0 + a1) + (a2 + a3);
        } else {
            int i = t - 2048;
            float a0 = bv[i], a1 = 0.f, a2 = 0.f, a3 = 0.f;
            for (int k = 0; k < 256; k += 4) {
                a0 = fmaf(nb2[k],     Wv[k * 256 + i],       a0);
                a1 = fmaf(nb2[k + 1], Wv[(k + 1) * 256 + i], a1);
                a2 = fmaf(nb2[k + 2], Wv[(k + 2) * 256 + i], a2);
                a3 = fmaf(nb2[k + 3], Wv[(k + 3) * 256 + i], a3);
            }
            g_c1[i] = (a0 + a1) + (a2 + a3);
        }
    }
    __syncthreads();

    // stage B: V = Wv@U ; c2 = c1@Wo + bo
    for (int t = tid; t < 2304; t += 1024) {
        if (t < 2048) {
            int i = t >> 3, d = t & 7;
            float a0 = 0.f, a1 = 0.f, a2 = 0.f, a3 = 0.f;
            for (int k = 0; k < 256; k += 4) {
                a0 = fmaf(Wv[i * 256 + k],     g_U[k * 8 + d],       a0);
                a1 = fmaf(Wv[i * 256 + k + 1], g_U[(k + 1) * 8 + d], a1);
                a2 = fmaf(Wv[i * 256 + k + 2], g_U[(k + 2) * 8 + d], a2);
                a3 = fmaf(Wv[i * 256 + k + 3], g_U[(k + 3) * 8 + d], a3);
            }
            g_V[t] = (a0 + a1) + (a2 + a3);
        } else {
            int i = t - 2048;
            float a0 = bo[i], a1 = 0.f, a2 = 0.f, a3 = 0.f;
            for (int k = 0; k < 256; k += 4) {
                a0 = fmaf(g_c1[k],     Wo[k * 256 + i],       a0);
                a1 = fmaf(g_c1[k + 1], Wo[(k + 1) * 256 + i], a1);
                a2 = fmaf(g_c1[k + 2], Wo[(k + 2) * 256 + i], a2);
                a3 = fmaf(g_c1[k + 3], Wo[(k + 3) * 256 + i], a3);
            }
            g_c2[i] = (a0 + a1) + (a2 + a3);
        }
    }
    __syncthreads();

    // stage C: M = nW2@V ; c3 = c2@Wp + bp
    for (int t = tid; t < 2056; t += 1024) {
        if (t < 2048) {
            int i = t >> 3, d = t & 7;
            float a0 = 0.f, a1 = 0.f, a2 = 0.f, a3 = 0.f;
            for (int k = 0; k < 256; k += 4) {
                a0 = fmaf(nW2[i * 256 + k],     g_V[k * 8 + d],       a0);
                a1 = fmaf(nW2[i * 256 + k + 1], g_V[(k + 1) * 8 + d], a1);
                a2 = fmaf(nW2[i * 256 + k + 2], g_V[(k + 2) * 8 + d], a2);
                a3 = fmaf(nW2[i * 256 + k + 3], g_V[(k + 3) * 8 + d], a3);
            }
            g_M[t] = (a0 + a1) + (a2 + a3);
        } else {
            int d = t - 2048;
            float acc = bp[d];
            for (int k = 0; k < 256; k++) acc = fmaf(g_c2[k], Wp[k * 8 + d], acc);
            g_c3[d] = acc;
        }
    }
    __syncthreads();

    // finalize BN: fold into g_Mg / const8
    __shared__ float sh[256];
    if (tid < 256) {
        int j = tid;
        float s = 0.f, q = 0.f;
        for (int b = 0; b < STATS_BLOCKS; b++) {
            s += g_part[b * 512 + j];
            q += g_part[b * 512 + 256 + j];
        }
        float mu = s * invE;
        float var = q * invE - mu * mu;
        float gg = gamma[j] * rsqrtf(var + 1e-5f);
        sh[j] = beta[j] - mu * gg;
#pragma unroll
        for (int d = 0; d < 8; d++) g_Mg[j * 8 + d] = gg * g_M[j * 8 + d];
    }
    __syncthreads();
    if (tid < 256) {
        int w = tid >> 5, lane = tid & 31;   // warp w -> const8[w]
        float acc = 0.f;
        for (int jj = lane; jj < 256; jj += 32) acc += sh[jj] * g_M[jj * 8 + w];
#pragma unroll
        for (int off = 16; off; off >>= 1)
            acc += __shfl_xor_sync(0xffffffffu, acc, off);
        if (lane == 0) g_const8[w] = acc + g_c3[w];
    }
}

// ---- pass 2: output, 1 edge/thread, recompute h, y = h @ Mg ---------------
__global__ void __launch_bounds__(256, 3) kOut(
    const float* __restrict__ nf, const int* __restrict__ ei,
    const float* __restrict__ W1, const float* __restrict__ b1,
    const float* __restrict__ ea, float* __restrict__ out, int E) {
    __shared__ ulonglong2 sW01[256];        // col j: (w0,w1),(w2,w3) * 0.5
    __shared__ ulonglong2 sW45[256];        // col j: (w4,w5),(w6,w7) * 0.5
    __shared__ ulonglong2 sM0[256];         // col j: (m0,m1),(m2,m3)
    __shared__ ulonglong2 sM4[256];         // col j: (m4,m5),(m6,m7)
    __shared__ unsigned long long sB2[256]; // (b1[j], 0)
    __shared__ unsigned long long sC[4];

    int tid = threadIdx.x;
    for (int j = tid; j < 256; j += 256) {
        ulonglong2 va, vb;
        va.x = pk2(0.5f * W1[0 * 256 + j], 0.5f * W1[1 * 256 + j]);
        va.y = pk2(0.5f * W1[2 * 256 + j], 0.5f * W1[3 * 256 + j]);
        vb.x = pk2(0.5f * W1[4 * 256 + j], 0.5f * W1[5 * 256 + j]);
        vb.y = pk2(0.5f * W1[6 * 256 + j], 0.5f * W1[7 * 256 + j]);
        sW01[j] = va;
        sW45[j] = vb;
        sM0[j] = ((const ulonglong2*)g_Mg)[2 * j];
        sM4[j] = ((const ulonglong2*)g_Mg)[2 * j + 1];
        sB2[j] = pk2(b1[j], 0.f);
    }
    if (tid < 4) sC[tid] = ((const unsigned long long*)g_const8)[tid];
    __syncthreads();

    int e = blockIdx.x * 256 + tid;
    if (e >= E) return;

    int a = ei[e], b = ei[E + e];
    const ulonglong4* nfq = (const ulonglong4*)nf;
    ulonglong4 A0 = nfq[a], B0 = nfq[b];

    unsigned long long c[4];
    ADD2(c[0], A0.x, B0.x); ADD2(c[1], A0.y, B0.y);
    ADD2(c[2], A0.z, B0.z); ADD2(c[3], A0.w, B0.w);

    unsigned long long y[4];
#pragma unroll
    for (int d = 0; d < 4; d++) y[d] = 0ull;

#pragma unroll 4
    for (int j = 0; j < 256; j++) {
        ulonglong2 wA = sW01[j];
        ulonglong2 wB = sW45[j];
        unsigned long long b2 = sB2[j];
        unsigned long long t;
        float lo, hi;
        FMA2(t, c[0], wA.x, b2);
        FMA2(t, c[1], wA.y, t);
        FMA2(t, c[2], wB.x, t);
        FMA2(t, c[3], wB.y, t);
        upk2(t, lo, hi);
        float h = fmaxf(lo + hi, 0.f);
        unsigned long long h2 = pk2(h, h);
        ulonglong2 m0 = sM0[j], m1 = sM4[j];
        FMA2(y[0], h2, m0.x, y[0]);
        FMA2(y[1], h2, m0.y, y[1]);
        FMA2(y[2], h2, m1.x, y[2]);
        FMA2(y[3], h2, m1.y, y[3]);
    }

    const unsigned long long H2 = HALF2C;
    const ulonglong4* eaq = (const ulonglong4*)ea;
    ulonglong4* outq = (ulonglong4*)out;
    ulonglong4 ev = eaq[e];
    ulonglong4 ov;
    unsigned long long t;
    ADD2(t, y[0], sC[0]); FMA2(ov.x, t, H2, ev.x);
    ADD2(t, y[1], sC[1]); FMA2(ov.y, t, H2, ev.y);
    ADD2(t, y[2], sC[2]); FMA2(ov.z, t, H2, ev.z);
    ADD2(t, y[3], sC[3]); FMA2(ov.w, t, H2, ev.w);
    outq[e] = ov;
}

// ---------------------------------------------------------------------------
extern "C" void kernel_launch(void* const* d_in, const int* in_sizes, int n_in,
                              void* d_out, int out_size) {
    const float* edge_attr = (const float*)d_in[0];
    const float* nf        = (const float*)d_in[1];
    const int*   ei        = (const int*)d_in[2];
    // d_in[3..8]: edge-encoder params (dead code in reference)
    const float* nW1   = (const float*)d_in[9];
    const float* nb1   = (const float*)d_in[10];
    const float* ngam  = (const float*)d_in[11];
    const float* nbet  = (const float*)d_in[12];
    const float* nW2   = (const float*)d_in[13];
    const float* nb2   = (const float*)d_in[14];
    const float* Wv    = (const float*)d_in[15];
    const float* bv    = (const float*)d_in[16];
    const float* Wo    = (const float*)d_in[17];
    const float* bo    = (const float*)d_in[18];
    const float* Wp    = (const float*)d_in[19];
    const float* bp    = (const float*)d_in[20];
    float* out = (float*)d_out;

    int E = in_sizes[0] / 8;

    kStats<<<STATS_BLOCKS, 128>>>(nf, ei, nW1, nb1, E);
    kFoldFin<<<1, 1024>>>(Wo, Wp, nb2, Wv, bv, bo, nW2, bp, ngam, nbet,
                          1.0f / (float)E);
    kOut<<<(E + 255) / 256, 256>>>(nf, ei, nW1, nb1, edge_attr, out, E);
}

// round 9
// speedup vs baseline: 1.6490x; 1.6490x over previous
#include <cuda_runtime.h>

// ---------------------------------------------------------------------------
// CausalEdgeAttention — algebraically reduced, 2-pass recompute.
//   out = edge_attr + 0.5*((relu(ctx@W1+b1) * g) @ M + const8)
//   ctx = 0.5*(nf[src]+nf[tgt]);  M = n_W2@Wv@Wo@Wp (256x8)
// R8: kStats = tiled-ctx (stage ctx tile in smem, thread-per-column compute,
//     weights in regs, broadcast LDS only). kOut = R1 proven structure.
// ---------------------------------------------------------------------------

#define STATS_BLOCKS 592               // 4 blocks/SM * 148 SMs, one wave
#define TILE 256

__device__ __align__(16) float g_U[256 * 8];
__device__ __align__(16) float g_V[256 * 8];
__device__ __align__(16) float g_M[256 * 8];
__device__ __align__(16) float g_Mg[256 * 8];
__device__ float g_c1[256];
__device__ float g_c2[256];
__device__ float g_c3[8];
__device__ __align__(16) float g_const8[8];
__device__ __align__(16) float g_part[STATS_BLOCKS * 512];

// ---- packed f32x2 helpers -------------------------------------------------
__device__ __forceinline__ unsigned long long pk2(float lo, float hi) {
    unsigned long long r;
    asm("mov.b64 %0, {%1, %2};" : "=l"(r) : "f"(lo), "f"(hi));
    return r;
}
__device__ __forceinline__ void upk2(unsigned long long v, float& lo, float& hi) {
    asm("mov.b64 {%0, %1}, %2;" : "=f"(lo), "=f"(hi) : "l"(v));
}
#define FMA2(d, a, b, c) asm("fma.rn.f32x2 %0, %1, %2, %3;" : "=l"(d) : "l"(a), "l"(b), "l"(c))
#define ADD2(d, a, b)    asm("add.rn.f32x2 %0, %1, %2;" : "=l"(d) : "l"(a), "l"(b))

// ---- pass 1: tiled-ctx batch stats of h = relu(ctx@W1+b1) -----------------
// Stage: thread t gathers edge (ts+t)'s two node rows, writes ctx to smem.
// Compute: thread j owns column j; broadcast-reads ctx[t]; weights in regs.
__global__ void __launch_bounds__(256) kStats(
    const float* __restrict__ nf, const int* __restrict__ ei,
    const float* __restrict__ W1, const float* __restrict__ b1, int E) {
    __shared__ unsigned long long sCtx[2][TILE][4];   // 16KB, (a+b) packed f32x2

    int tid = threadIdx.x;
    int j = tid;                         // owned column

    // weights for column j, 0.5 folded (ctx stored as a+b)
    unsigned long long w01 = pk2(0.5f * W1[0 * 256 + j], 0.5f * W1[1 * 256 + j]);
    unsigned long long w23 = pk2(0.5f * W1[2 * 256 + j], 0.5f * W1[3 * 256 + j]);
    unsigned long long w45 = pk2(0.5f * W1[4 * 256 + j], 0.5f * W1[5 * 256 + j]);
    unsigned long long w67 = pk2(0.5f * W1[6 * 256 + j], 0.5f * W1[7 * 256 + j]);
    unsigned long long b2 = pk2(b1[j], 0.f);

    float s = 0.f, q = 0.f;

    int per = (E + STATS_BLOCKS - 1) / STATS_BLOCKS;
    int start = blockIdx.x * per;
    int len = min(per, E - start);
    int nt = (len + TILE - 1) / TILE;

    const ulonglong4* nfq = (const ulonglong4*)nf;

    // stage tile 0
    {
        int e = start + tid;
        if (tid < len) {
            int a = ei[e], b = ei[E + e];
            ulonglong4 A = nfq[a], B = nfq[b];
            unsigned long long c0, c1, c2, c3;
            ADD2(c0, A.x, B.x); ADD2(c1, A.y, B.y);
            ADD2(c2, A.z, B.z); ADD2(c3, A.w, B.w);
            sCtx[0][tid][0] = c0; sCtx[0][tid][1] = c1;
            sCtx[0][tid][2] = c2; sCtx[0][tid][3] = c3;
        }
    }

    for (int t = 0; t < nt; t++) {
        __syncthreads();            // stage(t) visible to all

        // stage tile t+1 into the other buffer (overlaps compute of tile t)
        if (t + 1 < nt) {
            int e = start + (t + 1) * TILE + tid;
            if (e < start + len) {
                int buf = (t + 1) & 1;
                int a = ei[e], b = ei[E + e];
                ulonglong4 A = nfq[a], B = nfq[b];
                unsigned long long c0, c1, c2, c3;
                ADD2(c0, A.x, B.x); ADD2(c1, A.y, B.y);
                ADD2(c2, A.z, B.z); ADD2(c3, A.w, B.w);
                sCtx[buf][tid][0] = c0; sCtx[buf][tid][1] = c1;
                sCtx[buf][tid][2] = c2; sCtx[buf][tid][3] = c3;
            }
        }

        // compute tile t: column j over tlen edges, broadcast LDS only
        int buf = t & 1;
        int tlen = min(TILE, len - t * TILE);
        const ulonglong2* cb = (const ulonglong2*)&sCtx[buf][0][0];
#pragma unroll 4
        for (int tt = 0; tt < tlen; tt++) {
            ulonglong2 c01 = cb[2 * tt];
            ulonglong2 c23 = cb[2 * tt + 1];
            unsigned long long acc;
            FMA2(acc, c01.x, w01, b2);
            FMA2(acc, c01.y, w23, acc);
            FMA2(acc, c23.x, w45, acc);
            FMA2(acc, c23.y, w67, acc);
            float lo, hi;
            upk2(acc, lo, hi);
            float h = fmaxf(lo + hi, 0.f);
            s += h;
            q = fmaf(h, h, q);
        }
    }

    g_part[blockIdx.x * 512 + tid] = s;
    g_part[blockIdx.x * 512 + 256 + tid] = q;
}

// ---- weight folding + BN finalize, single kernel --------------------------
__global__ void __launch_bounds__(1024) kFoldFin(
    const float* __restrict__ Wo, const float* __restrict__ Wp,
    const float* __restrict__ nb2, const float* __restrict__ Wv,
    const float* __restrict__ bv, const float* __restrict__ bo,
    const float* __restrict__ nW2, const float* __restrict__ bp,
    const float* __restrict__ gamma, const float* __restrict__ beta,
    float invE) {
    int tid = threadIdx.x;

    // stage A: U = Wo@Wp ; c1 = nb2@Wv + bv
    for (int t = tid; t < 2304; t += 1024) {
        if (t < 2048) {
            int i = t >> 3, d = t & 7;
            float a0 = 0.f, a1 = 0.f, a2 = 0.f, a3 = 0.f;
            for (int k = 0; k < 256; k += 4) {
                a0 = fmaf(Wo[i * 256 + k],     Wp[k * 8 + d],       a0);
                a1 = fmaf(Wo[i * 256 + k + 1], Wp[(k + 1) * 8 + d], a1);
                a2 = fmaf(Wo[i * 256 + k + 2], Wp[(k + 2) * 8 + d], a2);
                a3 = fmaf(Wo[i * 256 + k + 3], Wp[(k + 3) * 8 + d], a3);
            }
            g_U[t] = (a0 + a1) + (a2 + a3);
        } else {
            int i = t - 2048;
            float a0 = bv[i], a1 = 0.f, a2 = 0.f, a3 = 0.f;
            for (int k = 0; k < 256; k += 4) {
                a0 = fmaf(nb2[k],     Wv[k * 256 + i],       a0);
                a1 = fmaf(nb2[k + 1], Wv[(k + 1) * 256 + i], a1);
                a2 = fmaf(nb2[k + 2], Wv[(k + 2) * 256 + i], a2);
                a3 = fmaf(nb2[k + 3], Wv[(k + 3) * 256 + i], a3);
            }
            g_c1[i] = (a0 + a1) + (a2 + a3);
        }
    }
    __syncthreads();

    // stage B: V = Wv@U ; c2 = c1@Wo + bo
    for (int t = tid; t < 2304; t += 1024) {
        if (t < 2048) {
            int i = t >> 3, d = t & 7;
            float a0 = 0.f, a1 = 0.f, a2 = 0.f, a3 = 0.f;
            for (int k = 0; k < 256; k += 4) {
                a0 = fmaf(Wv[i * 256 + k],     g_U[k * 8 + d],       a0);
                a1 = fmaf(Wv[i * 256 + k + 1], g_U[(k + 1) * 8 + d], a1);
                a2 = fmaf(Wv[i * 256 + k + 2], g_U[(k + 2) * 8 + d], a2);
                a3 = fmaf(Wv[i * 256 + k + 3], g_U[(k + 3) * 8 + d], a3);
            }
            g_V[t] = (a0 + a1) + (a2 + a3);
        } else {
            int i = t - 2048;
            float a0 = bo[i], a1 = 0.f, a2 = 0.f, a3 = 0.f;
            for (int k = 0; k < 256; k += 4) {
                a0 = fmaf(g_c1[k],     Wo[k * 256 + i],       a0);
                a1 = fmaf(g_c1[k + 1], Wo[(k + 1) * 256 + i], a1);
                a2 = fmaf(g_c1[k + 2], Wo[(k + 2) * 256 + i], a2);
                a3 = fmaf(g_c1[k + 3], Wo[(k + 3) * 256 + i], a3);
            }
            g_c2[i] = (a0 + a1) + (a2 + a3);
        }
    }
    __syncthreads();

    // stage C: M = nW2@V ; c3 = c2@Wp + bp
    for (int t = tid; t < 2056; t += 1024) {
        if (t < 2048) {
            int i = t >> 3, d = t & 7;
            float a0 = 0.f, a1 = 0.f, a2 = 0.f, a3 = 0.f;
            for (int k = 0; k < 256; k += 4) {
                a0 = fmaf(nW2[i * 256 + k],     g_V[k * 8 + d],       a0);
                a1 = fmaf(nW2[i * 256 + k + 1], g_V[(k + 1) * 8 + d], a1);
                a2 = fmaf(nW2[i * 256 + k + 2], g_V[(k + 2) * 8 + d], a2);
                a3 = fmaf(nW2[i * 256 + k + 3], g_V[(k + 3) * 8 + d], a3);
            }
            g_M[t] = (a0 + a1) + (a2 + a3);
        } else {
            int d = t - 2048;
            float acc = bp[d];
            for (int k = 0; k < 256; k++) acc = fmaf(g_c2[k], Wp[k * 8 + d], acc);
            g_c3[d] = acc;
        }
    }
    __syncthreads();

    // finalize BN: fold into g_Mg / const8
    __shared__ float sh[256];
    if (tid < 256) {
        int j = tid;
        float s = 0.f, q = 0.f;
        for (int b = 0; b < STATS_BLOCKS; b++) {
            s += g_part[b * 512 + j];
            q += g_part[b * 512 + 256 + j];
        }
        float mu = s * invE;
        float var = q * invE - mu * mu;
        float gg = gamma[j] * rsqrtf(var + 1e-5f);
        sh[j] = beta[j] - mu * gg;
#pragma unroll
        for (int d = 0; d < 8; d++) g_Mg[j * 8 + d] = gg * g_M[j * 8 + d];
    }
    __syncthreads();
    if (tid < 256) {
        int w = tid >> 5, lane = tid & 31;   // warp w -> const8[w]
        float acc = 0.f;
        for (int jj = lane; jj < 256; jj += 32) acc += sh[jj] * g_M[jj * 8 + w];
#pragma unroll
        for (int off = 16; off; off >>= 1)
            acc += __shfl_xor_sync(0xffffffffu, acc, off);
        if (lane == 0) g_const8[w] = acc + g_c3[w];
    }
}

// ---- pass 2: output, thread-per-edge (proven R1 structure) ----------------
__global__ void __launch_bounds__(256) kOut(
    const float* __restrict__ nf, const int* __restrict__ ei,
    const float* __restrict__ W1, const float* __restrict__ b1,
    const float* __restrict__ ea, float* __restrict__ out, int E) {
    __shared__ float4 sW[512];  // W1 transposed: row j = 8 floats
    __shared__ float4 sM[512];  // g-scaled M: row j = 8 floats
    __shared__ float sB[256];
    __shared__ float sC[8];

    int tid = threadIdx.x;
    float* sWf = (float*)sW;
    float* sMf = (float*)sM;
    for (int i = tid; i < 2048; i += 256) {
        int j = i >> 3, d = i & 7;
        sWf[i] = W1[d * 256 + j];
        sMf[i] = g_Mg[i];
    }
    sB[tid] = b1[tid];
    if (tid < 8) sC[tid] = g_const8[tid];
    __syncthreads();

    int e = blockIdx.x * 256 + tid;
    if (e >= E) return;

    int a = ei[e], b = ei[E + e];
    const float4* nf4 = (const float4*)nf;
    float4 a0 = nf4[a * 2], a1 = nf4[a * 2 + 1];
    float4 b0 = nf4[b * 2], b1v = nf4[b * 2 + 1];
    float c[8];
    c[0] = 0.5f * (a0.x + b0.x); c[1] = 0.5f * (a0.y + b0.y);
    c[2] = 0.5f * (a0.z + b0.z); c[3] = 0.5f * (a0.w + b0.w);
    c[4] = 0.5f * (a1.x + b1v.x); c[5] = 0.5f * (a1.y + b1v.y);
    c[6] = 0.5f * (a1.z + b1v.z); c[7] = 0.5f * (a1.w + b1v.w);

    float y[8];
#pragma unroll
    for (int d = 0; d < 8; d++) y[d] = 0.f;

#pragma unroll 8
    for (int j = 0; j < 256; j++) {
        float4 w0 = sW[j * 2], w1 = sW[j * 2 + 1];
        float h = sB[j];
        h += c[0] * w0.x; h += c[1] * w0.y; h += c[2] * w0.z; h += c[3] * w0.w;
        h += c[4] * w1.x; h += c[5] * w1.y; h += c[6] * w1.z; h += c[7] * w1.w;
        h = fmaxf(h, 0.f);
        float4 m0 = sM[j * 2], m1 = sM[j * 2 + 1];
        y[0] += h * m0.x; y[1] += h * m0.y; y[2] += h * m0.z; y[3] += h * m0.w;
        y[4] += h * m1.x; y[5] += h * m1.y; y[6] += h * m1.z; y[7] += h * m1.w;
    }

    const float4* ea4 = (const float4*)ea;
    float4 e0 = ea4[e * 2], e1 = ea4[e * 2 + 1];
    float4 o0, o1;
    o0.x = e0.x + 0.5f * (y[0] + sC[0]);
    o0.y = e0.y + 0.5f * (y[1] + sC[1]);
    o0.z = e0.z + 0.5f * (y[2] + sC[2]);
    o0.w = e0.w + 0.5f * (y[3] + sC[3]);
    o1.x = e1.x + 0.5f * (y[4] + sC[4]);
    o1.y = e1.y + 0.5f * (y[5] + sC[5]);
    o1.z = e1.z + 0.5f * (y[6] + sC[6]);
    o1.w = e1.w + 0.5f * (y[7] + sC[7]);
    float4* out4 = (float4*)out;
    out4[e * 2] = o0;
    out4[e * 2 + 1] = o1;
}

// ---------------------------------------------------------------------------
extern "C" void kernel_launch(void* const* d_in, const int* in_sizes, int n_in,
                              void* d_out, int out_size) {
    const float* edge_attr = (const float*)d_in[0];
    const float* nf        = (const float*)d_in[1];
    const int*   ei        = (const int*)d_in[2];
    // d_in[3..8]: edge-encoder params (dead code in reference)
    const float* nW1   = (const float*)d_in[9];
    const float* nb1   = (const float*)d_in[10];
    const float* ngam  = (const float*)d_in[11];
    const float* nbet  = (const float*)d_in[12];
    const float* nW2   = (const float*)d_in[13];
    const float* nb2   = (const float*)d_in[14];
    const float* Wv    = (const float*)d_in[15];
    const float* bv    = (const float*)d_in[16];
    const float* Wo    = (const float*)d_in[17];
    const float* bo    = (const float*)d_in[18];
    const float* Wp    = (const float*)d_in[19];
    const float* bp    = (const float*)d_in[20];
    float* out = (float*)d_out;

    int E = in_sizes[0] / 8;

    kStats<<<STATS_BLOCKS, 256>>>(nf, ei, nW1, nb1, E);
    kFoldFin<<<1, 1024>>>(Wo, Wp, nb2, Wv, bv, bo, nW2, bp, ngam, nbet,
                          1.0f / (float)E);
    kOut<<<(E + 255) / 256, 256>>>(nf, ei, nW1, nb1, edge_attr, out, E);
}